// round 14
// baseline (speedup 1.0000x reference)
#include <cuda_runtime.h>

// ---------------------------------------------------------------------------
// LSTM_88244398063643  (T=4096, I=H=1024)
//   Phase 1: xW = x @ W + bias  (fp32 SIMT GEMM, f32x2 FMA, BK=16)
//   Phase 2: sequential scan, 128 persistent blocks, U in registers.
//     Exchange = R11 (proven): 8-way replicated h buffers + flag lines;
//     producer lane r writes replica r (.cg), fence.acq_rel.gpu, relaxed
//     flag store.
//     R14 change (only): per-warp detection — each warp's lanes 0-7 spin
//     on its own 8 producers' flags, per-warp fence, then fetch. The step
//     is still closed by ONE symmetric __syncthreads (no free-running
//     barrier structures; no acquire loads).
// ---------------------------------------------------------------------------

#define T_STEPS 4096
#define H_DIM   1024
#define I_DIM   1024
#define G4      4096
#define NBLK    128
#define NTHR    512
#define NWARP   16
#define NREP    8
#define FSTRIDE 32            // flag padding: 32 uints = one 128B line

typedef unsigned long long ull;
typedef unsigned int uint;

__device__ float    g_xW[(size_t)T_STEPS * G4];          // 64 MB scratch
__device__ __align__(16) float g_hbuf[2][NREP][H_DIM];   // h, 8 replicas
__device__ __align__(128) uint g_flags[NREP * NBLK * FSTRIDE];
__device__ unsigned g_cnt0, g_cnt1;                      // end-of-kernel reset

// ---------------- f32x2 helpers --------------------------------------------
__device__ __forceinline__ ull fma2(ull a, ull b, ull c) {
    ull d; asm("fma.rn.f32x2 %0,%1,%2,%3;" : "=l"(d) : "l"(a), "l"(b), "l"(c)); return d;
}
__device__ __forceinline__ ull add2(ull a, ull b) {
    ull d; asm("add.rn.f32x2 %0,%1,%2;" : "=l"(d) : "l"(a), "l"(b)); return d;
}
__device__ __forceinline__ ull dup2(float x) {
    ull d; asm("mov.b64 %0,{%1,%1};" : "=l"(d) : "f"(x)); return d;
}
__device__ __forceinline__ ull pack2(float lo, float hi) {
    ull d; asm("mov.b64 %0,{%1,%2};" : "=l"(d) : "f"(lo), "f"(hi)); return d;
}
__device__ __forceinline__ float2 unpack2(ull v) {
    float lo, hi; asm("mov.b64 {%0,%1},%2;" : "=f"(lo), "=f"(hi) : "l"(v));
    return make_float2(lo, hi);
}

// ---------------- memory ops (proven set only) ------------------------------
__device__ __forceinline__ uint ld_rlx_u32(const uint* p) {
    uint v;
    asm volatile("ld.relaxed.gpu.global.u32 %0,[%1];" : "=r"(v) : "l"(p) : "memory");
    return v;
}
__device__ __forceinline__ void st_rlx_u32(uint* p, uint v) {
    asm volatile("st.relaxed.gpu.global.u32 [%0],%1;" :: "l"(p), "r"(v) : "memory");
}
__device__ __forceinline__ void stcg4(void* p, uint4 v) {
    asm volatile("st.global.cg.v4.u32 [%0],{%1,%2,%3,%4};"
                 :: "l"(p), "r"(v.x), "r"(v.y), "r"(v.z), "r"(v.w) : "memory");
}

// ---------------- fast activations -----------------------------------------
__device__ __forceinline__ float sigf(float x) {
    return 1.f / (1.f + __expf(-x));
}
__device__ __forceinline__ float tanh_fast(float x) {
    x = fminf(fmaxf(x, -15.f), 15.f);
    float e = __expf(-2.f * x);
    return __fdividef(1.f - e, 1.f + e);
}

// ============================ Phase 1: GEMM ================================
#define BM 128
#define BN 128
#define BK 16

__global__ __launch_bounds__(256, 2) void gemm_xw_kernel(
    const float* __restrict__ A,      // x [4096,1024]
    const float* __restrict__ B,      // W [1024,4096]
    const float* __restrict__ bias)   // [4096]
{
    __shared__ float As[BK][BM];
    __shared__ float Bs[BK][BN];

    const int bx = blockIdx.x, by = blockIdx.y, tid = threadIdx.x;
    const int tx = tid & 15, ty = tid >> 4;

    ull acc[8][4];
#pragma unroll
    for (int i = 0; i < 8; i++)
#pragma unroll
        for (int j = 0; j < 4; j++) acc[i][j] = 0ull;

    const int aRow = tid >> 1, aCol = (tid & 1) * 8;
    const int bRow = tid >> 4, bCol = (tid & 15) * 8;
    const float* Aptr = A + (size_t)(by * BM + aRow) * I_DIM + aCol;
    const float* Bptr = B + (size_t)bRow * G4 + bx * BN + bCol;

    float4 a0 = *(const float4*)(Aptr);
    float4 a1 = *(const float4*)(Aptr + 4);
    float4 b0 = *(const float4*)(Bptr);
    float4 b1 = *(const float4*)(Bptr + 4);

    int k0 = 0;
    for (;;) {
        As[aCol + 0][aRow] = a0.x; As[aCol + 1][aRow] = a0.y;
        As[aCol + 2][aRow] = a0.z; As[aCol + 3][aRow] = a0.w;
        As[aCol + 4][aRow] = a1.x; As[aCol + 5][aRow] = a1.y;
        As[aCol + 6][aRow] = a1.z; As[aCol + 7][aRow] = a1.w;
        *(float4*)&Bs[bRow][bCol]     = b0;
        *(float4*)&Bs[bRow][bCol + 4] = b1;
        __syncthreads();

        k0 += BK;
        const bool more = (k0 < I_DIM);
        if (more) {
            a0 = *(const float4*)(Aptr + k0);
            a1 = *(const float4*)(Aptr + k0 + 4);
            b0 = *(const float4*)(Bptr + (size_t)k0 * G4);
            b1 = *(const float4*)(Bptr + (size_t)k0 * G4 + 4);
        }

#pragma unroll
        for (int k = 0; k < BK; k++) {
            float4 af0 = *(const float4*)&As[k][ty * 8];
            float4 af1 = *(const float4*)&As[k][ty * 8 + 4];
            ulonglong2 bb0 = *(const ulonglong2*)&Bs[k][tx * 8];
            ulonglong2 bb1 = *(const ulonglong2*)&Bs[k][tx * 8 + 4];
            float ar[8] = {af0.x, af0.y, af0.z, af0.w, af1.x, af1.y, af1.z, af1.w};
            ull bp[4] = {bb0.x, bb0.y, bb1.x, bb1.y};
#pragma unroll
            for (int i = 0; i < 8; i++) {
                ull aa = dup2(ar[i]);
                acc[i][0] = fma2(aa, bp[0], acc[i][0]);
                acc[i][1] = fma2(aa, bp[1], acc[i][1]);
                acc[i][2] = fma2(aa, bp[2], acc[i][2]);
                acc[i][3] = fma2(aa, bp[3], acc[i][3]);
            }
        }
        if (!more) break;
        __syncthreads();
    }

#pragma unroll
    for (int i = 0; i < 8; i++) {
        const size_t row = (size_t)(by * BM + ty * 8 + i);
        float* crow = g_xW + row * G4 + bx * BN + tx * 8;
        const float* brow = bias + bx * BN + tx * 8;
#pragma unroll
        for (int j2 = 0; j2 < 4; j2++) {
            float2 c = unpack2(acc[i][j2]);
            crow[2 * j2]     = c.x + brow[2 * j2];
            crow[2 * j2 + 1] = c.y + brow[2 * j2 + 1];
        }
    }
}

// ========================= Phase 2: recurrence =============================
// lane = gate*8 + unit; block owns hidden units [blk*8, blk*8+8)

__device__ __forceinline__ void lstm_update(
    float s, int t, int lane, int blk,
    float& c_state, float& h_last, float* __restrict__ out)
{
    float gf = __shfl_sync(0xffffffffu, s, (lane + 8) & 31);
    float gg = __shfl_sync(0xffffffffu, s, (lane + 16) & 31);
    float go = __shfl_sync(0xffffffffu, s, (lane + 24) & 31);
    float hv = 0.f;
    if (lane < 8) {
        float iv = sigf(s);
        float fv = sigf(gf);
        float gv = tanh_fast(gg);
        float ov = sigf(go);
        c_state = fv * c_state + iv * gv;
        hv = ov * tanh_fast(c_state);
        h_last = hv;
    }
    // broadcast h0..h7 to ALL lanes; lane r (<8) publishes replica r
    float h0 = __shfl_sync(0xffffffffu, hv, 0);
    float h1 = __shfl_sync(0xffffffffu, hv, 1);
    float h2 = __shfl_sync(0xffffffffu, hv, 2);
    float h3 = __shfl_sync(0xffffffffu, hv, 3);
    float h4 = __shfl_sync(0xffffffffu, hv, 4);
    float h5 = __shfl_sync(0xffffffffu, hv, 5);
    float h6 = __shfl_sync(0xffffffffu, hv, 6);
    float h7 = __shfl_sync(0xffffffffu, hv, 7);
    if (lane < NREP) {
        float* hb = &g_hbuf[t & 1][lane][blk * 8];
        uint4 d0, d1;
        d0.x = __float_as_uint(h0); d0.y = __float_as_uint(h1);
        d0.z = __float_as_uint(h2); d0.w = __float_as_uint(h3);
        d1.x = __float_as_uint(h4); d1.y = __float_as_uint(h5);
        d1.z = __float_as_uint(h6); d1.w = __float_as_uint(h7);
        stcg4(hb, d0);
        stcg4(hb + 4, d1);
    }
    // per-thread ordering: each lane's data stores drain before its flag
    asm volatile("fence.acq_rel.gpu;" ::: "memory");
    if (lane < NREP) {
        st_rlx_u32(&g_flags[(size_t)(lane * NBLK + blk) * FSTRIDE], (uint)(t + 1));
    }
    if (lane < 8) out[(size_t)t * H_DIM + blk * 8 + lane] = hv;
}

__global__ __launch_bounds__(NTHR, 1) void lstm_rec_kernel(
    const float* __restrict__ U,      // [1024, 4096] row-major
    float* __restrict__ out,
    long long out_size)
{
    __shared__ __align__(16) float hs[H_DIM];
    __shared__ float part[2][NWARP][32];

    const int tid = threadIdx.x;
    const int wid = tid >> 5;
    const int lane = tid & 31;
    const int blk = blockIdx.x;
    const int rep = blk & (NREP - 1);
    const int unit = lane & 7;
    const int gate = lane >> 3;
    const int gcol = gate * H_DIM + blk * 8 + unit;

    // U slice into registers as packed f32x2 pairs: k = wid*64 + 2j, 2j+1
    ull Ur2[32];
    {
        const float* up = U + (size_t)(wid * 64) * G4 + gcol;
#pragma unroll
        for (int j = 0; j < 32; j++) {
            float lo = up[(size_t)(2 * j) * G4];
            float hi = up[(size_t)(2 * j + 1) * G4];
            Ur2[j] = pack2(lo, hi);
        }
    }

    float c_state = 0.f, h_last = 0.f;

    // ---- step 0: gates = xW[0] (h = 0); warp 0 publishes h_0 ----
    if (wid == 0) {
        float s = g_xW[gcol];
        lstm_update(s, 0, lane, blk, c_state, h_last, out);
    }

    for (int t = 1; t < T_STEPS; t++) {
        // prefetch xW[t][gcol] (independent; covered by the spin)
        float xw = 0.f;
        if (wid == 0) xw = __ldg(g_xW + (size_t)t * G4 + gcol);

        // --- per-warp detect: lanes 0-7 spin on this warp's 8 producers ---
        {
            const uint need = (uint)t;
            if (lane < 8) {
                const uint* fp =
                    &g_flags[(size_t)(rep * NBLK + wid * 8 + lane) * FSTRIDE];
                while (ld_rlx_u32(fp) < need) { }
            }
            __syncwarp();
            // fence between detection and data read (binding empirical law)
            asm volatile("fence.acq_rel.gpu;" ::: "memory");
        }

        // --- fetch h[64w .. 64w+64) from replica rep, stage to smem ---
        // (hs region is per-warp private; __syncwarp suffices)
        {
            const float2* hb = (const float2*)&g_hbuf[(t - 1) & 1][rep][wid << 6];
            float2 hv = __ldcg(hb + lane);
            *(float2*)&hs[(wid << 6) + 2 * lane] = hv;
        }
        __syncwarp();

        // --- dot: broadcast LDS.128, packed f32x2 FMA ---
        ull a0 = 0ull, a1 = 0ull, a2 = 0ull, a3 = 0ull;
        const ulonglong2* h4 = (const ulonglong2*)&hs[wid << 6];
#pragma unroll
        for (int i = 0; i < 8; i++) {
            ulonglong2 p = h4[2 * i];
            ulonglong2 q = h4[2 * i + 1];
            a0 = fma2(Ur2[4 * i + 0], p.x, a0);
            a1 = fma2(Ur2[4 * i + 1], p.y, a1);
            a2 = fma2(Ur2[4 * i + 2], q.x, a2);
            a3 = fma2(Ur2[4 * i + 3], q.y, a3);
        }
        float2 sv = unpack2(add2(add2(a0, a2), add2(a1, a3)));
        part[t & 1][wid][lane] = sv.x + sv.y;

        __syncthreads();   // symmetric block-wide close of the step

        // --- warp 0: cross-warp reduce, activations, publish ---
        if (wid == 0) {
            const float* p = &part[t & 1][0][lane];
            float q0 = p[0 * 32] + p[1 * 32];
            float q1 = p[2 * 32] + p[3 * 32];
            float q2 = p[4 * 32] + p[5 * 32];
            float q3 = p[6 * 32] + p[7 * 32];
            float q4 = p[8 * 32] + p[9 * 32];
            float q5 = p[10 * 32] + p[11 * 32];
            float q6 = p[12 * 32] + p[13 * 32];
            float q7 = p[14 * 32] + p[15 * 32];
            float r0 = q0 + q1, r1 = q2 + q3, r2 = q4 + q5, r3 = q6 + q7;
            float s = xw + ((r0 + r1) + (r2 + r3));
            lstm_update(s, t, lane, blk, c_state, h_last, out);
        }
    }

    // ---- tail: h_T, c_T ----
    if (wid == 0 && lane < 8 &&
        (size_t)out_size >= (size_t)T_STEPS * H_DIM + 2 * H_DIM) {
        out[(size_t)T_STEPS * H_DIM + blk * 8 + lane] = h_last;
        out[(size_t)T_STEPS * H_DIM + H_DIM + blk * 8 + lane] = c_state;
    }

    // ---- replay-safe flag reset (two-counter ticket barrier, proven) ----
    __syncthreads();
    if (tid == 0) {
        __threadfence();
        atomicAdd(&g_cnt0, 1u);
        unsigned v;
        do {
            v = ld_rlx_u32(&g_cnt0);
        } while (v < (unsigned)NBLK);
#pragma unroll
        for (int r = 0; r < NREP; r++)
            asm volatile("st.global.cg.u32 [%0], %1;"
                         :: "l"(&g_flags[(size_t)(r * NBLK + blk) * FSTRIDE]),
                            "r"(0u) : "memory");
        __threadfence();
        if (atomicAdd(&g_cnt1, 1u) == (unsigned)(NBLK - 1)) {
            asm volatile("st.global.cg.u32 [%0], %1;" :: "l"(&g_cnt0), "r"(0u) : "memory");
            asm volatile("st.global.cg.u32 [%0], %1;" :: "l"(&g_cnt1), "r"(0u) : "memory");
        }
    }
}

// =============================== launch ====================================
extern "C" void kernel_launch(void* const* d_in, const int* in_sizes, int n_in,
                              void* d_out, int out_size)
{
    const float* x    = (const float*)d_in[0];
    const float* W    = (const float*)d_in[1];
    const float* U    = (const float*)d_in[2];
    const float* bias = (const float*)d_in[3];
    float* out = (float*)d_out;

    dim3 ggrid(G4 / BN, T_STEPS / BM);
    gemm_xw_kernel<<<ggrid, 256>>>(x, W, bias);

    lstm_rec_kernel<<<NBLK, NTHR>>>(U, out, (long long)out_size);
}

// round 16
// speedup vs baseline: 2.5277x; 2.5277x over previous
#include <cuda_runtime.h>

// ---------------------------------------------------------------------------
// LSTM_88244398063643  (T=4096, I=H=1024)
//   Phase 1: xW = x @ W + bias  (fp32 SIMT GEMM, f32x2 FMA, BK=16)
//   Phase 2: sequential scan, 128 persistent blocks, U in registers.
//     Exchange: ONE-ROUND self-validating 64-bit words.
//       Each h value is published as a single aligned 64-bit word
//       (tag<<32 | fp32 bits) via st.relaxed.gpu.u64 (strong => atomic,
//       L1-coherent). Consumers spin with ld.relaxed.gpu.u64 on exactly
//       their own words: detection and data are the SAME load. No fences,
//       no flags, no acquire, no named barriers in the hot loop.
//       8 replicas (block b reads replica b&7); parity double buffer;
//       ONE symmetric __syncthreads per step.
// ---------------------------------------------------------------------------

#define T_STEPS 4096
#define H_DIM   1024
#define I_DIM   1024
#define G4      4096
#define NBLK    128
#define NTHR    512
#define NWARP   16
#define NREP    8

typedef unsigned long long ull;
typedef unsigned int uint;

__device__ float g_xW[(size_t)T_STEPS * G4];          // 64 MB scratch
// tagged h words: [parity][replica][block*8 + unit] = (tag<<32 | h_bits)
__device__ __align__(16) ull g_pub[2][NREP][H_DIM];   // 128 KB
__device__ unsigned g_cnt0, g_cnt1;                   // end-of-kernel reset

// ---------------- f32x2 helpers --------------------------------------------
__device__ __forceinline__ ull fma2(ull a, ull b, ull c) {
    ull d; asm("fma.rn.f32x2 %0,%1,%2,%3;" : "=l"(d) : "l"(a), "l"(b), "l"(c)); return d;
}
__device__ __forceinline__ ull add2(ull a, ull b) {
    ull d; asm("add.rn.f32x2 %0,%1,%2;" : "=l"(d) : "l"(a), "l"(b)); return d;
}
__device__ __forceinline__ ull dup2(float x) {
    ull d; asm("mov.b64 %0,{%1,%1};" : "=l"(d) : "f"(x)); return d;
}
__device__ __forceinline__ ull pack2(float lo, float hi) {
    ull d; asm("mov.b64 %0,{%1,%2};" : "=l"(d) : "f"(lo), "f"(hi)); return d;
}
__device__ __forceinline__ float2 unpack2(ull v) {
    float lo, hi; asm("mov.b64 {%0,%1},%2;" : "=f"(lo), "=f"(hi) : "l"(v));
    return make_float2(lo, hi);
}

// ---------------- strong 64-bit ops (atomic, L1-coherent) --------------------
__device__ __forceinline__ ull ld_rlx_u64(const ull* p) {
    ull v;
    asm volatile("ld.relaxed.gpu.global.u64 %0,[%1];" : "=l"(v) : "l"(p) : "memory");
    return v;
}
__device__ __forceinline__ void st_rlx_u64(ull* p, ull v) {
    asm volatile("st.relaxed.gpu.global.u64 [%0],%1;" :: "l"(p), "l"(v) : "memory");
}
__device__ __forceinline__ uint ld_rlx_u32(const uint* p) {
    uint v;
    asm volatile("ld.relaxed.gpu.global.u32 %0,[%1];" : "=r"(v) : "l"(p) : "memory");
    return v;
}

// ---------------- fast activations -----------------------------------------
__device__ __forceinline__ float sigf(float x) {
    return 1.f / (1.f + __expf(-x));
}
__device__ __forceinline__ float tanh_fast(float x) {
    x = fminf(fmaxf(x, -15.f), 15.f);
    float e = __expf(-2.f * x);
    return __fdividef(1.f - e, 1.f + e);
}

// ============================ Phase 1: GEMM ================================
#define BM 128
#define BN 128
#define BK 16

__global__ __launch_bounds__(256, 2) void gemm_xw_kernel(
    const float* __restrict__ A,      // x [4096,1024]
    const float* __restrict__ B,      // W [1024,4096]
    const float* __restrict__ bias)   // [4096]
{
    __shared__ float As[BK][BM];
    __shared__ float Bs[BK][BN];

    const int bx = blockIdx.x, by = blockIdx.y, tid = threadIdx.x;
    const int tx = tid & 15, ty = tid >> 4;

    ull acc[8][4];
#pragma unroll
    for (int i = 0; i < 8; i++)
#pragma unroll
        for (int j = 0; j < 4; j++) acc[i][j] = 0ull;

    const int aRow = tid >> 1, aCol = (tid & 1) * 8;
    const int bRow = tid >> 4, bCol = (tid & 15) * 8;
    const float* Aptr = A + (size_t)(by * BM + aRow) * I_DIM + aCol;
    const float* Bptr = B + (size_t)bRow * G4 + bx * BN + bCol;

    float4 a0 = *(const float4*)(Aptr);
    float4 a1 = *(const float4*)(Aptr + 4);
    float4 b0 = *(const float4*)(Bptr);
    float4 b1 = *(const float4*)(Bptr + 4);

    int k0 = 0;
    for (;;) {
        As[aCol + 0][aRow] = a0.x; As[aCol + 1][aRow] = a0.y;
        As[aCol + 2][aRow] = a0.z; As[aCol + 3][aRow] = a0.w;
        As[aCol + 4][aRow] = a1.x; As[aCol + 5][aRow] = a1.y;
        As[aCol + 6][aRow] = a1.z; As[aCol + 7][aRow] = a1.w;
        *(float4*)&Bs[bRow][bCol]     = b0;
        *(float4*)&Bs[bRow][bCol + 4] = b1;
        __syncthreads();

        k0 += BK;
        const bool more = (k0 < I_DIM);
        if (more) {
            a0 = *(const float4*)(Aptr + k0);
            a1 = *(const float4*)(Aptr + k0 + 4);
            b0 = *(const float4*)(Bptr + (size_t)k0 * G4);
            b1 = *(const float4*)(Bptr + (size_t)k0 * G4 + 4);
        }

#pragma unroll
        for (int k = 0; k < BK; k++) {
            float4 af0 = *(const float4*)&As[k][ty * 8];
            float4 af1 = *(const float4*)&As[k][ty * 8 + 4];
            ulonglong2 bb0 = *(const ulonglong2*)&Bs[k][tx * 8];
            ulonglong2 bb1 = *(const ulonglong2*)&Bs[k][tx * 8 + 4];
            float ar[8] = {af0.x, af0.y, af0.z, af0.w, af1.x, af1.y, af1.z, af1.w};
            ull bp[4] = {bb0.x, bb0.y, bb1.x, bb1.y};
#pragma unroll
            for (int i = 0; i < 8; i++) {
                ull aa = dup2(ar[i]);
                acc[i][0] = fma2(aa, bp[0], acc[i][0]);
                acc[i][1] = fma2(aa, bp[1], acc[i][1]);
                acc[i][2] = fma2(aa, bp[2], acc[i][2]);
                acc[i][3] = fma2(aa, bp[3], acc[i][3]);
            }
        }
        if (!more) break;
        __syncthreads();
    }

#pragma unroll
    for (int i = 0; i < 8; i++) {
        const size_t row = (size_t)(by * BM + ty * 8 + i);
        float* crow = g_xW + row * G4 + bx * BN + tx * 8;
        const float* brow = bias + bx * BN + tx * 8;
#pragma unroll
        for (int j2 = 0; j2 < 4; j2++) {
            float2 c = unpack2(acc[i][j2]);
            crow[2 * j2]     = c.x + brow[2 * j2];
            crow[2 * j2 + 1] = c.y + brow[2 * j2 + 1];
        }
    }
}

// ========================= Phase 2: recurrence =============================
// lane = gate*8 + unit; block owns hidden units [blk*8, blk*8+8)

__device__ __forceinline__ void lstm_update(
    float s, int t, int lane, int blk,
    float& c_state, float& h_last, float* __restrict__ out)
{
    float gf = __shfl_sync(0xffffffffu, s, (lane + 8) & 31);
    float gg = __shfl_sync(0xffffffffu, s, (lane + 16) & 31);
    float go = __shfl_sync(0xffffffffu, s, (lane + 24) & 31);
    float hv = 0.f;
    if (lane < 8) {
        float iv = sigf(s);
        float fv = sigf(gf);
        float gv = tanh_fast(gg);
        float ov = sigf(go);
        c_state = fv * c_state + iv * gv;
        hv = ov * tanh_fast(c_state);
        h_last = hv;
    }
    // publish: 64 tagged words (8 replicas x 8 units), 2 per lane.
    // lane l handles replica r = l>>2, units u0=(l&3)*2 and u0+1.
    {
        const int u0 = (lane & 3) * 2;
        const int r  = lane >> 2;
        float a = __shfl_sync(0xffffffffu, hv, u0);
        float b = __shfl_sync(0xffffffffu, hv, u0 + 1);
        const ull tag = ((ull)(uint)(t + 1)) << 32;   // 1..4096, nonzero
        ull* dst = &g_pub[t & 1][r][blk * 8 + u0];
        st_rlx_u64(dst,     tag | (ull)__float_as_uint(a));
        st_rlx_u64(dst + 1, tag | (ull)__float_as_uint(b));
    }
    if (lane < 8) out[(size_t)t * H_DIM + blk * 8 + lane] = hv;
}

__global__ __launch_bounds__(NTHR, 1) void lstm_rec_kernel(
    const float* __restrict__ U,      // [1024, 4096] row-major
    float* __restrict__ out,
    long long out_size)
{
    __shared__ __align__(16) float hs[H_DIM];
    __shared__ float part[2][NWARP][32];

    const int tid = threadIdx.x;
    const int wid = tid >> 5;
    const int lane = tid & 31;
    const int blk = blockIdx.x;
    const int rep = blk & (NREP - 1);
    const int unit = lane & 7;
    const int gate = lane >> 3;
    const int gcol = gate * H_DIM + blk * 8 + unit;

    // U slice into registers as packed f32x2 pairs: k = wid*64 + 2j, 2j+1
    ull Ur2[32];
    {
        const float* up = U + (size_t)(wid * 64) * G4 + gcol;
#pragma unroll
        for (int j = 0; j < 32; j++) {
            float lo = up[(size_t)(2 * j) * G4];
            float hi = up[(size_t)(2 * j + 1) * G4];
            Ur2[j] = pack2(lo, hi);
        }
    }

    float c_state = 0.f, h_last = 0.f;

    // ---- step 0: gates = xW[0] (h = 0); warp 0 publishes h_0 (tag 1) ----
    if (wid == 0) {
        float s = g_xW[gcol];
        lstm_update(s, 0, lane, blk, c_state, h_last, out);
    }

    for (int t = 1; t < T_STEPS; t++) {
        // prefetch xW[t][gcol] (independent; covered by the spin)
        float xw = 0.f;
        if (wid == 0) xw = __ldg(g_xW + (size_t)t * G4 + gcol);

        // --- one-round fetch: lane l spins on its own 2 tagged words ---
        // h_{t-1} carries tag t. Detection and data are the same load.
        {
            const ull need = ((ull)(uint)t) << 32;
            const ull* p = &g_pub[(t - 1) & 1][rep][(wid << 6) + 2 * lane];
            ull v0, v1;
            for (;;) {
                v0 = ld_rlx_u64(p);
                v1 = ld_rlx_u64(p + 1);
                if ((v0 & 0xFFFFFFFF00000000ull) == need &&
                    (v1 & 0xFFFFFFFF00000000ull) == need) break;
            }
            *(float2*)&hs[(wid << 6) + 2 * lane] =
                make_float2(__uint_as_float((uint)v0), __uint_as_float((uint)v1));
        }
        __syncwarp();

        // --- dot: broadcast LDS.128, packed f32x2 FMA ---
        ull a0 = 0ull, a1 = 0ull, a2 = 0ull, a3 = 0ull;
        const ulonglong2* h4 = (const ulonglong2*)&hs[wid << 6];
#pragma unroll
        for (int i = 0; i < 8; i++) {
            ulonglong2 p = h4[2 * i];
            ulonglong2 q = h4[2 * i + 1];
            a0 = fma2(Ur2[4 * i + 0], p.x, a0);
            a1 = fma2(Ur2[4 * i + 1], p.y, a1);
            a2 = fma2(Ur2[4 * i + 2], q.x, a2);
            a3 = fma2(Ur2[4 * i + 3], q.y, a3);
        }
        float2 sv = unpack2(add2(add2(a0, a2), add2(a1, a3)));
        part[t & 1][wid][lane] = sv.x + sv.y;

        __syncthreads();   // the ONLY block-wide sync per step (symmetric)

        // --- warp 0: cross-warp reduce, activations, publish ---
        if (wid == 0) {
            const float* p = &part[t & 1][0][lane];
            float q0 = p[0 * 32] + p[1 * 32];
            float q1 = p[2 * 32] + p[3 * 32];
            float q2 = p[4 * 32] + p[5 * 32];
            float q3 = p[6 * 32] + p[7 * 32];
            float q4 = p[8 * 32] + p[9 * 32];
            float q5 = p[10 * 32] + p[11 * 32];
            float q6 = p[12 * 32] + p[13 * 32];
            float q7 = p[14 * 32] + p[15 * 32];
            float r0 = q0 + q1, r1 = q2 + q3, r2 = q4 + q5, r3 = q6 + q7;
            float s = xw + ((r0 + r1) + (r2 + r3));
            lstm_update(s, t, lane, blk, c_state, h_last, out);
        }
    }

    // ---- tail: h_T, c_T ----
    if (wid == 0 && lane < 8 &&
        (size_t)out_size >= (size_t)T_STEPS * H_DIM + 2 * H_DIM) {
        out[(size_t)T_STEPS * H_DIM + blk * 8 + lane] = h_last;
        out[(size_t)T_STEPS * H_DIM + H_DIM + blk * 8 + lane] = c_state;
    }

    // ---- replay-safe pub reset (two-counter ticket barrier, proven) ----
    // Phase 1 proves all blocks are past their last fetch; then each block
    // zeros its own 8 words in every (parity, replica) slot.
    __syncthreads();
    if (tid == 0) {
        __threadfence();
        atomicAdd(&g_cnt0, 1u);
        unsigned v;
        do {
            v = ld_rlx_u32(&g_cnt0);
        } while (v < (unsigned)NBLK);
#pragma unroll
        for (int pz = 0; pz < 2; pz++)
#pragma unroll
            for (int r = 0; r < NREP; r++) {
                ull* d = &g_pub[pz][r][blk * 8];
#pragma unroll
                for (int u = 0; u < 8; u++) st_rlx_u64(d + u, 0ull);
            }
        __threadfence();
        if (atomicAdd(&g_cnt1, 1u) == (unsigned)(NBLK - 1)) {
            asm volatile("st.global.cg.u32 [%0], %1;" :: "l"(&g_cnt0), "r"(0u) : "memory");
            asm volatile("st.global.cg.u32 [%0], %1;" :: "l"(&g_cnt1), "r"(0u) : "memory");
        }
    }
}

// =============================== launch ====================================
extern "C" void kernel_launch(void* const* d_in, const int* in_sizes, int n_in,
                              void* d_out, int out_size)
{
    const float* x    = (const float*)d_in[0];
    const float* W    = (const float*)d_in[1];
    const float* U    = (const float*)d_in[2];
    const float* bias = (const float*)d_in[3];
    float* out = (float*)d_out;

    dim3 ggrid(G4 / BN, T_STEPS / BM);
    gemm_xw_kernel<<<ggrid, 256>>>(x, W, bias);

    lstm_rec_kernel<<<NBLK, NTHR>>>(U, out, (long long)out_size);
}